// round 7
// baseline (speedup 1.0000x reference)
#include <cuda_runtime.h>
#include <cstdint>

typedef unsigned long long u64;
typedef unsigned int u32;

#define ROWS 8192
#define KDIM 3072
#define KHALF 1536
#define NOUT 64
#define KT   64                 // k per tile
#define NKT  24                 // tiles per K-half (1536/64)
#define STAGE_A 32768           // 128 rows * 64 f32
#define STAGE_B 16384           // 64 rows * 64 f32
#define STAGE   (STAGE_A + STAGE_B)
#define NSTAGE  3
#define SMEMSZ  (NSTAGE * STAGE)   // 147456

// ---- scratch (no allocation allowed) ----
__device__ __align__(16) float g_xwt[8 * NOUT * KDIM];     // B matrices, tf32-rounded
__device__ __align__(16) float g_cpart[2 * ROWS * NOUT];   // K-split partials
__device__ float g_zbuf[ROWS * NOUT];
__device__ float g_part[64 * NOUT];
__device__ float g_psq [64 * NOUT];
__device__ float g_scale[NOUT];
__device__ float g_shift[NOUT];

// ---- helpers ----
__device__ __forceinline__ u64 pack2(float a, float b){
    u64 r; asm("mov.b64 %0,{%1,%2};" : "=l"(r) : "f"(a), "f"(b)); return r;
}
__device__ __forceinline__ void unpack2(u64 v, float& a, float& b){
    asm("mov.b64 {%0,%1},%2;" : "=f"(a), "=f"(b) : "l"(v));
}
__device__ __forceinline__ u64 fma2(u64 a, u64 b, u64 c){
    u64 d; asm("fma.rn.f32x2 %0,%1,%2,%3;" : "=l"(d) : "l"(a), "l"(b), "l"(c)); return d;
}
__device__ __forceinline__ void cp16(char* smem_dst, const void* gsrc){
    unsigned s = (unsigned)__cvta_generic_to_shared(smem_dst);
    asm volatile("cp.async.cg.shared.global [%0], [%1], 16;" :: "r"(s), "l"(gsrc));
}
__device__ __forceinline__ u32 to_tf32(float f){
    u32 r; asm("cvt.rna.tf32.f32 %0,%1;" : "=r"(r) : "f"(f)); return r;
}
__device__ __forceinline__ void mma_tf32(float c[4], const u32 a[4], const u32 b[2]){
    asm volatile(
        "mma.sync.aligned.m16n8k8.row.col.f32.tf32.tf32.f32 "
        "{%0,%1,%2,%3}, {%4,%5,%6,%7}, {%8,%9}, {%0,%1,%2,%3};"
        : "+f"(c[0]), "+f"(c[1]), "+f"(c[2]), "+f"(c[3])
        : "r"(a[0]), "r"(a[1]), "r"(a[2]), "r"(a[3]), "r"(b[0]), "r"(b[1]));
}

// ============================================================================
// k_xw: XWT[b][n][m*3+j] = tf32( sum_f x[b,m,f] * Wc[n, j*32+f] )
// grid 512 = (b 8, n 64), block 64
// ============================================================================
__global__ __launch_bounds__(64)
void k_xw(const float* __restrict__ x, const float* __restrict__ W1,
          const float* __restrict__ W2)
{
    __shared__ __align__(16) float wcs[96];
    __shared__ u64 xsp[64][17];
    const int bidx = blockIdx.x;
    const int bb = bidx >> 6, n = bidx & 63;
    const int tid = threadIdx.x;

    const float* wr = (n < 32) ? (W1 + n * 96) : (W2 + (size_t)(n - 32) * 96);
    wcs[tid] = wr[tid];
    if (tid < 32) wcs[64 + tid] = wr[64 + tid];

    const float* xbp = x + (size_t)bb * 1024 * 32;
    float* outp = g_xwt + ((size_t)bb * NOUT + n) * KDIM;

    for (int ch = 0; ch < 16; ch++) {
        __syncthreads();
        #pragma unroll
        for (int i = 0; i < 8; i++) {
            int ml = (tid >> 3) + i * 8, fq = tid & 7;
            float4 v = *(const float4*)(xbp + (size_t)(ch * 64 + ml) * 32 + fq * 4);
            float* p = (float*)&xsp[ml][2 * fq];
            p[0] = v.x; p[1] = v.y; p[2] = v.z; p[3] = v.w;
        }
        __syncthreads();
        u64 xr[16];
        #pragma unroll
        for (int q = 0; q < 16; q++) xr[q] = xsp[tid][q];
        const u64* wcp = (const u64*)wcs;
        const int m = ch * 64 + tid;
        #pragma unroll
        for (int j = 0; j < 3; j++) {
            u64 a = 0ull;
            #pragma unroll
            for (int q = 0; q < 16; q++) a = fma2(wcp[j * 16 + q], xr[q], a);
            float lo, hi; unpack2(a, lo, hi);
            outp[m * 3 + j] = __uint_as_float(to_tf32(lo + hi));
        }
    }
}

// ============================================================================
// k_gemm: partial C[128,64] = A[128,1536] x B[64,1536]^T via mma.sync tf32
// grid 128 = (mblk 64) x (khalf 2), block 128 (4 warps x 32 rows)
// ============================================================================
__global__ __launch_bounds__(128, 1)
void k_gemm(const float* __restrict__ WW)
{
    extern __shared__ __align__(1024) char smem[];
    const int tid  = threadIdx.x;
    const int warp = tid >> 5, lane = tid & 31;
    const int g    = lane >> 2, t4 = lane & 3;
    const int kh   = blockIdx.x & 1;
    const int mblk = blockIdx.x >> 1;
    const int R0   = mblk * 128;
    const int bb   = mblk >> 3;
    const int koff = kh * KHALF;

    float acc[2][8][4];
    #pragma unroll
    for (int mt = 0; mt < 2; mt++)
        #pragma unroll
        for (int nt = 0; nt < 8; nt++)
            #pragma unroll
            for (int i = 0; i < 4; i++) acc[mt][nt][i] = 0.f;

    const float* Abase = WW + (size_t)R0 * KDIM + koff;
    const float* Bbase = g_xwt + (size_t)bb * NOUT * KDIM + koff;

    auto issue = [&](int t){
        char* sa = smem + (t % NSTAGE) * STAGE;
        char* sbm = sa + STAGE_A;
        const int k0 = t * KT;
        #pragma unroll
        for (int i = 0; i < 16; i++) {
            int c = tid + i * 128;                 // < 2048
            int rr = c >> 4, q = c & 15;
            cp16(sa + rr * 256 + ((q ^ (rr & 7)) * 16),
                 Abase + (size_t)rr * KDIM + k0 + q * 4);
        }
        #pragma unroll
        for (int i = 0; i < 8; i++) {
            int c = tid + i * 128;                 // < 1024
            int rr = c >> 4, q = c & 15;
            cp16(sbm + rr * 256 + ((q ^ (rr & 7)) * 16),
                 Bbase + (size_t)rr * KDIM + k0 + q * 4);
        }
        asm volatile("cp.async.commit_group;" ::: "memory");
    };

    issue(0); issue(1);

    const int xh = (g & 6) << 2;        // bits 3-4 of xor
    const int xl = (g & 1) << 2;        // bit 2 of xor
    const int kA = t4 ^ xl;
    const int kB = (t4 + 4) ^ xl;
    const int rb0 = (warp * 32 + g) * 64;

    #pragma unroll 1
    for (int t = 0; t < NKT; t++) {
        if (t + 1 < NKT) asm volatile("cp.async.wait_group 1;" ::: "memory");
        else             asm volatile("cp.async.wait_group 0;" ::: "memory");
        __syncthreads();
        if (t + 2 < NKT) issue(t + 2);

        const float* As = (const float*)(smem + (t % NSTAGE) * STAGE);
        const u32*   Bs = (const u32*)  (smem + (t % NSTAGE) * STAGE + STAGE_A);

        #pragma unroll
        for (int s = 0; s < 8; s++) {
            const int v  = (8 * s) ^ xh;
            const int o1 = v + kA, o2 = v + kB;
            u32 a[2][4];
            #pragma unroll
            for (int mt = 0; mt < 2; mt++) {
                const int rb = rb0 + mt * 1024;          // (row+16)*64
                a[mt][0] = to_tf32(As[rb + o1]);
                a[mt][1] = to_tf32(As[rb + 512 + o1]);   // row+8
                a[mt][2] = to_tf32(As[rb + o2]);
                a[mt][3] = to_tf32(As[rb + 512 + o2]);
            }
            u32 b[8][2];
            #pragma unroll
            for (int nt = 0; nt < 8; nt++) {
                const int nb = (nt * 8 + g) * 64;
                b[nt][0] = Bs[nb + o1];
                b[nt][1] = Bs[nb + o2];
            }
            #pragma unroll
            for (int mt = 0; mt < 2; mt++)
                #pragma unroll
                for (int nt = 0; nt < 8; nt++)
                    mma_tf32(acc[mt][nt], a[mt], b[nt]);
        }
    }

    // ---- write K-split partial ----
    float* cp = g_cpart + (size_t)kh * ROWS * NOUT;
    #pragma unroll
    for (int mt = 0; mt < 2; mt++) {
        const int row = R0 + warp * 32 + mt * 16 + g;
        #pragma unroll
        for (int nt = 0; nt < 8; nt++) {
            const int col = nt * 8 + 2 * t4;
            *(float2*)&cp[(size_t)row * 64 + col] =
                make_float2(acc[mt][nt][0], acc[mt][nt][1]);
            *(float2*)&cp[(size_t)(row + 8) * 64 + col] =
                make_float2(acc[mt][nt][2], acc[mt][nt][3]);
        }
    }
}

// ============================================================================
// k_combine: z = c0 + c1 + bias (relu on first 32), zbuf + BN partials
// grid 64, block 256
// ============================================================================
__global__ __launch_bounds__(256)
void k_combine(const float* __restrict__ b1, const float* __restrict__ b2)
{
    __shared__ float bias[64];
    __shared__ float ps[256], pq[256];
    const int tid = threadIdx.x;
    if (tid < 32)       bias[tid] = b1[tid];
    else if (tid < 64)  bias[tid] = b2[tid - 32];
    __syncthreads();

    const int k  = tid & 63;
    const int rh = tid >> 6;                  // 0..3
    const float bk = bias[k];
    float ls = 0.f, lsq = 0.f;
    const int base = blockIdx.x * 128;
    #pragma unroll 4
    for (int i = 0; i < 32; i++) {
        const size_t idx = (size_t)(base + rh + 4 * i) * 64 + k;
        float z = g_cpart[idx] + g_cpart[(size_t)ROWS * NOUT + idx] + bk;
        if (k < 32) z = fmaxf(z, 0.f);
        g_zbuf[idx] = z;
        ls += z; lsq += z * z;
    }
    ps[tid] = ls; pq[tid] = lsq;
    __syncthreads();
    if (tid < 64) {
        g_part[blockIdx.x * 64 + k] = ps[k] + ps[64 + k] + ps[128 + k] + ps[192 + k];
        g_psq [blockIdx.x * 64 + k] = pq[k] + pq[64 + k] + pq[128 + k] + pq[192 + k];
    }
}

// ============================================================================
__global__ __launch_bounds__(256)
void k_stats(const float* __restrict__ gamma, const float* __restrict__ beta)
{
    __shared__ float rs[256], rq[256];
    const int k = threadIdx.x & 63, g = threadIdx.x >> 6;
    float s = 0.f, sq = 0.f;
    for (int i = g * 16; i < g * 16 + 16; i++) {
        s  += g_part[i * 64 + k];
        sq += g_psq [i * 64 + k];
    }
    rs[threadIdx.x] = s; rq[threadIdx.x] = sq;
    __syncthreads();
    if (g == 0) {
        s  = rs[k] + rs[64 + k] + rs[128 + k] + rs[192 + k];
        sq = rq[k] + rq[64 + k] + rq[128 + k] + rq[192 + k];
        float mean = s / (float)ROWS;
        float var  = sq / (float)ROWS - mean * mean;
        float sc = gamma[k] * rsqrtf(var + 1e-5f);
        g_scale[k] = sc;
        g_shift[k] = beta[k] - mean * sc;
    }
}

__global__ __launch_bounds__(256)
void k_norm(float* __restrict__ out)
{
    __shared__ float sc[64], sh[64];
    int tid = threadIdx.x;
    if (tid < 64) { sc[tid] = g_scale[tid]; sh[tid] = g_shift[tid]; }
    __syncthreads();
    int i = blockIdx.x * 256 + tid;                 // float4 index, 131072 total
    float4 z = ((const float4*)g_zbuf)[i];
    int kb = (i & 15) * 4;
    float4 o;
    o.x = z.x * sc[kb+0] + sh[kb+0];
    o.y = z.y * sc[kb+1] + sh[kb+1];
    o.z = z.z * sc[kb+2] + sh[kb+2];
    o.w = z.w * sc[kb+3] + sh[kb+3];
    ((float4*)out)[i] = o;
}

extern "C" void kernel_launch(void* const* d_in, const int* in_sizes, int n_in,
                              void* d_out, int out_size)
{
    const float* WW    = (const float*)d_in[0];
    const float* x     = (const float*)d_in[1];
    const float* W1    = (const float*)d_in[2];
    const float* b1    = (const float*)d_in[3];
    const float* W2    = (const float*)d_in[4];
    const float* b2    = (const float*)d_in[5];
    const float* gamma = (const float*)d_in[6];
    const float* beta  = (const float*)d_in[7];
    float* out = (float*)d_out;

    cudaFuncSetAttribute(k_gemm, cudaFuncAttributeMaxDynamicSharedMemorySize, SMEMSZ);

    k_xw     <<<512, 64>>>(x, W1, W2);
    k_gemm   <<<128, 128, SMEMSZ>>>(WW);
    k_combine<<<64, 256>>>(b1, b2);
    k_stats  <<<1, 256>>>(gamma, beta);
    k_norm   <<<ROWS * NOUT / (256 * 4), 256>>>(out);
}